// round 16
// baseline (speedup 1.0000x reference)
#include <cuda_runtime.h>
#include <cuda_fp16.h>
#include <cstdint>

#define BN 16384
#define SEQ 32
#define RNN 64
#define NG 256
#define VOCAB 1001
#define TBM 32             // samples per LSTM CTA
#define EXACT_FROM 30      // steps >= this use full 3-product compensation
#define THREEFRY_PARTITIONABLE 1

typedef unsigned long long u64;

__device__ float g_tokgate[VOCAB * NG];
// Wlo B-fragments, pre-swizzled for coalesced warp loads:
// index ((nb*4+kt)*8+nt)*32 + lane
__device__ uint2 g_WloF[4 * 4 * 8 * 32];

// ================= threefry2x32 (exact JAX algorithm) =================
__host__ __device__ __forceinline__ uint32_t rotl32(uint32_t x, int d) {
    return (x << d) | (x >> (32 - d));
}
__host__ __device__ __forceinline__ void threefry2x32(uint32_t k0, uint32_t k1,
                                                      uint32_t c0, uint32_t c1,
                                                      uint32_t& o0, uint32_t& o1) {
    uint32_t ks2 = k0 ^ k1 ^ 0x1BD11BDAu;
    uint32_t x0 = c0 + k0, x1 = c1 + k1;
#define TF_R4(a,b,c,d) \
    x0 += x1; x1 = rotl32(x1,a); x1 ^= x0; \
    x0 += x1; x1 = rotl32(x1,b); x1 ^= x0; \
    x0 += x1; x1 = rotl32(x1,c); x1 ^= x0; \
    x0 += x1; x1 = rotl32(x1,d); x1 ^= x0;
    TF_R4(13,15,26,6);  x0 += k1;  x1 += ks2 + 1u;
    TF_R4(17,29,16,24); x0 += ks2; x1 += k0  + 2u;
    TF_R4(13,15,26,6);  x0 += k0;  x1 += k1  + 3u;
    TF_R4(17,29,16,24); x0 += k1;  x1 += ks2 + 4u;
    TF_R4(13,15,26,6);  x0 += ks2; x1 += k0  + 5u;
#undef TF_R4
    o0 = x0; o1 = x1;
}

struct Keys { uint32_t a[7]; uint32_t b[7]; };

__device__ __forceinline__ uint32_t jax_bits32(uint32_t k0, uint32_t k1,
                                               uint32_t idx, uint32_t half) {
#if THREEFRY_PARTITIONABLE
    uint32_t y0, y1;
    threefry2x32(k0, k1, 0u, idx, y0, y1);
    return y0 ^ y1;
#else
    uint32_t p = (idx < half) ? idx : idx - half;
    uint32_t y0, y1;
    threefry2x32(k0, k1, p, p + half, y0, y1);
    return (idx < half) ? y0 : y1;
#endif
}
__device__ __forceinline__ float jax_gumbel(uint32_t k0, uint32_t k1,
                                            uint32_t idx, uint32_t half) {
    uint32_t bits = jax_bits32(k0, k1, idx, half);
    float f = __uint_as_float((bits >> 9) | 0x3f800000u) - 1.0f;
    f = fmaxf(f, 1.17549435e-38f);
    return -logf(-logf(f));
}

// ---- MUFU-based fast activations (LSTM cell only) ----
__device__ __forceinline__ float fsig(float x) {
    return __fdividef(1.0f, 1.0f + __expf(-x));
}
__device__ __forceinline__ float ftanh(float x) {
    float xc = fminf(fmaxf(x, -12.0f), 12.0f);
    float t = __expf(2.0f * xc);
    return __fdividef(t - 1.0f, t + 1.0f);
}

// mma.sync m16n8k16 f16 (baseline PTX)
__device__ __forceinline__ void mma_f16(float d[4], const uint32_t a[4],
                                        uint32_t b0, uint32_t b1) {
    asm volatile(
        "mma.sync.aligned.m16n8k16.row.col.f32.f16.f16.f32 "
        "{%0,%1,%2,%3}, {%4,%5,%6,%7}, {%8,%9}, {%0,%1,%2,%3};"
        : "+f"(d[0]), "+f"(d[1]), "+f"(d[2]), "+f"(d[3])
        : "r"(a[0]), "r"(a[1]), "r"(a[2]), "r"(a[3]), "r"(b0), "r"(b1));
}

__device__ __forceinline__ uint32_t pack_h2(__half lo_h, __half hi_h) {
    __half2 h2 = __halves2half2(lo_h, hi_h);
    return *(uint32_t*)&h2;
}

// ================= tokgate precompute =================
__global__ void __launch_bounds__(256)
tokgate_kernel(const float* __restrict__ embed, const float* __restrict__ W_ih,
               const float* __restrict__ b_ih, const float* __restrict__ b_hh) {
    __shared__ float e[8][64];
    const int v0 = blockIdx.x * 8;
    const int tid = threadIdx.x;
    for (int i = tid; i < 8 * 64; i += 256) {
        int vv = v0 + (i >> 6);
        e[i >> 6][i & 63] = (vv < VOCAB) ? embed[vv * 64 + (i & 63)] : 0.f;
    }
    __syncthreads();
    const int c = tid, gg = c & 3, u = c >> 2;
    const int row = gg * 64 + u;
    float wreg[64];
    const float4* wp = (const float4*)(W_ih + row * 64);
#pragma unroll
    for (int i = 0; i < 16; i++) {
        float4 w4 = wp[i];
        wreg[4 * i] = w4.x; wreg[4 * i + 1] = w4.y;
        wreg[4 * i + 2] = w4.z; wreg[4 * i + 3] = w4.w;
    }
    const float bias = b_ih[row] + b_hh[row];
#pragma unroll
    for (int j = 0; j < 8; j++) {
        int v = v0 + j;
        if (v >= VOCAB) break;
        float d = bias;
#pragma unroll
        for (int k = 0; k < 64; k++) d = fmaf(e[j][k], wreg[k], d);
        g_tokgate[v * NG + c] = d;
    }
}

// ================= Wlo fragment table precompute =================
__global__ void __launch_bounds__(256)
wlof_kernel(const float* __restrict__ W_hh) {
    int idx = blockIdx.x * 256 + threadIdx.x;   // 0..4095
    int lane = idx & 31, nt = (idx >> 5) & 7, kt = (idx >> 8) & 3, nb = (idx >> 10) & 3;
    int gid = lane >> 2, tig = lane & 3;
    int c = nb * 64 + nt * 8 + gid;
    int cnb = c >> 6, cnt = (c >> 3) & 7, cup = (c >> 2) & 1, cg = c & 3;
    int u = cnb * 16 + cnt * 2 + cup;
    const float* wr = W_hh + (cg * 64 + u) * 64;
    uint2 v;
    {
        int kp = kt * 8 + tig;
        float w0 = wr[2 * kp], w1 = wr[2 * kp + 1];
        __half h0 = __float2half_rn(w0), h1 = __float2half_rn(w1);
        v.x = pack_h2(__float2half_rn(w0 - __half2float(h0)),
                      __float2half_rn(w1 - __half2float(h1)));
    }
    {
        int kp = kt * 8 + tig + 4;
        float w0 = wr[2 * kp], w1 = wr[2 * kp + 1];
        __half h0 = __float2half_rn(w0), h1 = __float2half_rn(w1);
        v.y = pack_h2(__float2half_rn(w0 - __half2float(h0)),
                      __float2half_rn(w1 - __half2float(h1)));
    }
    g_WloF[idx] = v;
}

// ================= fused LSTM + heads kernel =================
#define WSTR 36
#define OFF_WHI 0
#define OFF_H   (256 * WSTR)
#define OFF_TOK (OFF_H + 4 * TBM * WSTR)
#define LSTM_SMEM_WORDS (OFF_TOK + TBM * SEQ)
#define LSTM_SMEM_BYTES (LSTM_SMEM_WORDS * 4)
// column order: c' = nb*64 + nt*8 + 4*up + g ; unit u = nb*16 + nt*2 + up

// heads weight staging offsets inside the (dead after t-loop) Whi region
#define FW_WC   0
#define FW_BC   192
#define FW_WS   200
#define FW_BS   392
#define FW_WL   400      // dialog 0: 1600
#define FW_BL   2000     // dialog 0: 25
#define FW_WP   400      // dialog 1: 512
#define FW_BP   912      // dialog 1: 8
#define FW_WR1  1024     // dialog 1: 2176 (stride 68)
#define FW_BR1  3200
#define FW_WR2  3232
#define FW_BR2  3264

__device__ const int c_offx[8] = {-1, 1, 0, 0, -1, -1, 1, 1};
__device__ const int c_offy[8] = {0, 0, 1, -1, -1, 1, -1, 1};

// Pair-split categorical sample (proven in R12/R14)
template <int MAXC>
__device__ __forceinline__ int sample_lp_pair(const float* lg, int vbase, int vcnt,
                                              int V, uint32_t k0, uint32_t k1,
                                              int b, float& lp) {
    const uint32_t half = (uint32_t)(BN * V / 2);
    float bestz = -1e30f, bestl = -1e30f, m = -1e30f;
    int bestv = 0;
#pragma unroll
    for (int i = 0; i < MAXC; i++) {
        if (i >= vcnt) break;
        int v = vbase + i;
        float z = lg[i] + jax_gumbel(k0, k1, (uint32_t)(b * V + v), half);
        if (z > bestz) { bestz = z; bestv = v; bestl = lg[i]; }
        m = fmaxf(m, lg[i]);
    }
    m = fmaxf(m, __shfl_xor_sync(0xffffffffu, m, 1));
    float ssum = 0.f;
#pragma unroll
    for (int i = 0; i < MAXC; i++) {
        if (i >= vcnt) break;
        ssum += expf(lg[i] - m);
    }
    ssum += __shfl_xor_sync(0xffffffffu, ssum, 1);
    float zo = __shfl_xor_sync(0xffffffffu, bestz, 1);
    int   vo = __shfl_xor_sync(0xffffffffu, bestv, 1);
    float lo = __shfl_xor_sync(0xffffffffu, bestl, 1);
    if (zo > bestz) { bestv = vo; bestl = lo; }
    lp = (bestl - m) - logf(ssum);
    return bestv;
}

__global__ void __launch_bounds__(256, 3)
lstm_kernel(const int* __restrict__ inst0, const int* __restrict__ inst1,
            const float* __restrict__ W_hh,
            const int* __restrict__ canvas0, const int* __restrict__ canvas1,
            const int* __restrict__ refp,
            const float* __restrict__ Wc, const float* __restrict__ bc,
            const float* __restrict__ Ws, const float* __restrict__ bs,
            const float* __restrict__ Wl, const float* __restrict__ bl,
            const float* __restrict__ Wr1, const float* __restrict__ br1,
            const float* __restrict__ Wr2, const float* __restrict__ br2,
            const float* __restrict__ Wp, const float* __restrict__ bp,
            float* __restrict__ out, Keys keys) {
    extern __shared__ uint32_t smw[];
    uint32_t* Whi = smw + OFF_WHI;
    int*      tok = (int*)(smw + OFF_TOK);    // [s][t]

    const int tid  = threadIdx.x;
    const int wid  = tid >> 5, lane = tid & 31;
    const int gid  = lane >> 2, tig = lane & 3;
    const int mb   = wid & 1;
    const int nb   = wid >> 1;
    const int base = blockIdx.x * TBM;
    const int dialog = blockIdx.y;
    const int* inst = (dialog == 0) ? inst0 : inst1;

    for (int idx = tid; idx < NG * 32; idx += 256) {
        int c = idx >> 5, kp = idx & 31;
        int cnb = c >> 6, cnt = (c >> 3) & 7, cup = (c >> 2) & 1, cg = c & 3;
        int u = cnb * 16 + cnt * 2 + cup;
        const float* wr = W_hh + (cg * 64 + u) * 64 + 2 * kp;
        Whi[c * WSTR + kp] = pack_h2(__float2half_rn(wr[0]), __float2half_rn(wr[1]));
    }
    for (int idx = tid; idx < TBM * SEQ; idx += 256)
        tok[idx] = inst[base * SEQ + idx];
    __syncthreads();

    const int row   = mb * 16 + gid + 8 * (tig & 1);
    const int upair = tig >> 1;
    const int m0    = mb * 16;
    const int cn0   = nb * 64;
    // fp32 h for the heads phase: lives in the t=31 WRITE buffer region (buf 0),
    // disjoint from the t=31 READ buffer (buf 1).
    float* hbf = (float*)(smw + OFF_H);        // [32][65]
    float c_reg[8];
#pragma unroll
    for (int i = 0; i < 8; i++) c_reg[i] = 0.f;

    for (int t = 0; t < SEQ; t++) {
        uint32_t* Hr_hi = smw + OFF_H + (t & 1) * (2 * TBM * WSTR);
        uint32_t* Hr_lo = Hr_hi + TBM * WSTR;
        uint32_t* Hw_hi = smw + OFF_H + ((t + 1) & 1) * (2 * TBM * WSTR);
        uint32_t* Hw_lo = Hw_hi + TBM * WSTR;
        __half* HWh = (__half*)Hw_hi;
        __half* HWl = (__half*)Hw_lo;

        const int tv = tok[row * SEQ + t];
        const float4* tgp = (const float4*)(g_tokgate + tv * NG);

        float d[8][4];
#pragma unroll
        for (int nt = 0; nt < 8; nt++)
#pragma unroll
            for (int j = 0; j < 4; j++) d[nt][j] = 0.f;

        if (t > 0) {
            const bool exact = (t >= EXACT_FROM);
#pragma unroll
            for (int kt = 0; kt < 4; kt++) {
                const int kp0 = kt * 8 + tig;
                uint32_t ahi[4];
                ahi[0] = Hr_hi[(m0 + gid)     * WSTR + kp0];
                ahi[1] = Hr_hi[(m0 + gid + 8) * WSTR + kp0];
                ahi[2] = Hr_hi[(m0 + gid)     * WSTR + kp0 + 4];
                ahi[3] = Hr_hi[(m0 + gid + 8) * WSTR + kp0 + 4];

                uint32_t bh[8][2];
#pragma unroll
                for (int nt = 0; nt < 8; nt++) {
                    const int c = cn0 + nt * 8 + gid;
                    bh[nt][0] = Whi[c * WSTR + kp0];
                    bh[nt][1] = Whi[c * WSTR + kp0 + 4];
                    mma_f16(d[nt], ahi, bh[nt][0], bh[nt][1]);   // hi . Whi
                }
                if (exact) {
                    uint32_t alo[4];
                    alo[0] = Hr_lo[(m0 + gid)     * WSTR + kp0];
                    alo[1] = Hr_lo[(m0 + gid + 8) * WSTR + kp0];
                    alo[2] = Hr_lo[(m0 + gid)     * WSTR + kp0 + 4];
                    alo[3] = Hr_lo[(m0 + gid + 8) * WSTR + kp0 + 4];
#pragma unroll
                    for (int nt = 0; nt < 8; nt++)
                        mma_f16(d[nt], alo, bh[nt][0], bh[nt][1]);  // lo . Whi
                    const uint2* wlo = g_WloF + ((nb * 4 + kt) * 8) * 32 + lane;
#pragma unroll
                    for (int nt = 0; nt < 8; nt++) {
                        uint2 bl = wlo[nt * 32];                    // coalesced LDG.64
                        mma_f16(d[nt], ahi, bl.x, bl.y);            // hi . Wlo
                    }
                }
            }
        }

        // ---- epilogue: 2-shfl quad-exchange, + tokgate, LSTM cell (MUFU), store ----
        const bool e = (tig & 1) == 0;
        const bool store_lo = (t >= EXACT_FROM - 1) && (t < SEQ - 1);
        const bool last = (t == SEQ - 1);

#pragma unroll
        for (int nt = 0; nt < 8; nt++) {
            float x0 = e ? d[nt][2] : d[nt][0];
            float x1 = e ? d[nt][3] : d[nt][1];
            float s0 = __shfl_xor_sync(0xffffffffu, x0, 1);
            float s1 = __shfl_xor_sync(0xffffffffu, x1, 1);
            float ig = e ? d[nt][0] : s0;
            float fg = e ? d[nt][1] : s1;
            float gg = e ? s0 : d[nt][2];
            float og = e ? s1 : d[nt][3];
            const int u = nb * 16 + nt * 2 + upair;
            float4 tgv = tgp[u];
            ig += tgv.x; fg += tgv.y; gg += tgv.z; og += tgv.w;
            float cb = fsig(fg) * c_reg[nt] + fsig(ig) * ftanh(gg);
            float h = fsig(og) * ftanh(cb);
            c_reg[nt] = cb;
            if (last) {
                hbf[row * 65 + u] = h;          // fp32 h for heads (buf 0 region)
            } else {
                __half hh = __float2half_rn(h);
                HWh[row * (2 * WSTR) + u] = hh;
                if (store_lo)
                    HWl[row * (2 * WSTR) + u] = __float2half_rn(h - __half2float(hh));
            }
        }
        __syncthreads();
    }

    // ================== fused heads phase ==================
    // Stage head weights into the dead Whi region (all 256 threads).
    float* ws = (float*)smw;
    for (int i = tid; i < 192;  i += 256) ws[FW_WC + i] = Wc[i];
    for (int i = tid; i < 192;  i += 256) ws[FW_WS + i] = Ws[i];
    if (tid < 3) ws[FW_BC + tid] = bc[tid];
    if (tid < 3) ws[FW_BS + tid] = bs[tid];
    if (dialog == 0) {
        for (int i = tid; i < 1600; i += 256) ws[FW_WL + i] = Wl[i];
        if (tid < 25) ws[FW_BL + tid] = bl[tid];
    } else {
        for (int i = tid; i < 512;  i += 256) ws[FW_WP + i] = Wp[i];
        for (int i = tid; i < 2176; i += 256) ws[FW_WR1 + i] = Wr1[i];
        if (tid < 8)  ws[FW_BP + tid]  = bp[tid];
        if (tid < 32) ws[FW_BR1 + tid] = br1[tid];
        if (tid < 32) ws[FW_WR2 + tid] = Wr2[tid];
        if (tid == 0) ws[FW_BR2] = br2[0];
    }
    __syncthreads();

    if (tid >= 64) return;   // warps 2..7 retire; warps 0..1 run heads

    const int p    = tid & 1;
    const int sidx = tid >> 1;           // 0..31
    const int b    = base + sidx;
    const float* h = hbf + sidx * 65;

    // color/shape logits, split 2/1 across the pair
    const int cbase = p ? 2 : 0;
    const int ccnt  = p ? 1 : 2;
    float lgc[2], lgs[2];
#pragma unroll
    for (int i = 0; i < 2; i++) {
        if (i >= ccnt) break;
        int r = cbase + i;
        float dd = 0.f, ee = 0.f;
        for (int k = 0; k < 64; k++) {
            dd = fmaf(h[k], ws[FW_WC + r * 64 + k], dd);
            ee = fmaf(h[k], ws[FW_WS + r * 64 + k], ee);
        }
        lgc[i] = dd + ws[FW_BC + r];
        lgs[i] = ee + ws[FW_BS + r];
    }

    const int lbase = p ? 13 : 0;
    const int lcnt  = p ? 12 : 13;

    if (dialog == 0) {
        float ll[13];
#pragma unroll
        for (int i = 0; i < 13; i++) {
            if (i >= lcnt) break;
            int r = lbase + i;
            float dd = 0.f;
            for (int k = 0; k < 64; k++) dd = fmaf(h[k], ws[FW_WL + r * 64 + k], dd);
            ll[i] = dd + ws[FW_BL + r];
        }
        float clp0, slp0, llp0;
        int cs0  = sample_lp_pair<2>(lgc, cbase, ccnt, 3, keys.a[0], keys.b[0], b, clp0);
        sample_lp_pair<2>(lgs, cbase, ccnt, 3, keys.a[1], keys.b[1], b, slp0);
        int loc0 = sample_lp_pair<13>(ll, lbase, lcnt, 25, keys.a[2], keys.b[2], b, llp0);

        if (p == 0) {
            int lclip = min(max(loc0, 0), 24);
            int4 pt = *(const int4*)(canvas1 + (b * 25 + lclip) * 4);
            bool ok0 = (loc0 >= 0) && (loc0 < 25) && ((pt.x + pt.y + pt.z + pt.w) >= 0);
            float loc_r0 = ok0 ? 1.f : -1.f;
            float col_r0 = ok0 ? ((cs0 == pt.x) ? 1.f : -1.f) : 0.f;

            out[0 * BN + b] = clp0;
            out[1 * BN + b] = slp0;
            out[2 * BN + b] = llp0;
            out[(7 + 0) * BN + b] = loc_r0;
            out[(7 + 1) * BN + b] = col_r0;
            out[(7 + 2) * BN + b] = loc_r0;
        }
    } else {
        float lp8[4];
        const int pbase = p * 4;
#pragma unroll
        for (int i = 0; i < 4; i++) {
            int r = pbase + i;
            float dd = 0.f;
            for (int k = 0; k < 64; k++) dd = fmaf(h[k], ws[FW_WP + r * 64 + k], dd);
            lp8[i] = dd + ws[FW_BP + r];
        }
        float clp1, slp1, llp1, alp1;
        int cs1 = sample_lp_pair<2>(lgc, cbase, ccnt, 3, keys.a[3], keys.b[3], b, clp1);
        sample_lp_pair<2>(lgs, cbase, ccnt, 3, keys.a[4], keys.b[4], b, slp1);
        int ls1 = sample_lp_pair<4>(lp8, pbase, 4, 8, keys.a[5], keys.b[5], b, llp1);

        const int j0 = p * 16;
        float pre[16];
#pragma unroll
        for (int jj = 0; jj < 16; jj++) {
            int j = j0 + jj;
            float dd = 0.f;
            for (int k = 0; k < 64; k++) dd = fmaf(h[k], ws[FW_WR1 + j * 68 + k], dd);
            pre[jj] = dd + ws[FW_BR1 + j];
        }
        float alsh[13];
#pragma unroll 5
        for (int loc = 0; loc < 25; loc++) {
            int4 cv = *(const int4*)(canvas0 + (b * 25 + loc) * 4);
            float cx = (float)cv.x, cy = (float)cv.y, cz = (float)cv.z, cw = (float)cv.w;
            float partial = p ? 0.f : ws[FW_BR2];
#pragma unroll
            for (int jj = 0; jj < 16; jj++) {
                int j = j0 + jj;
                float v = pre[jj];
                v = fmaf(cx, ws[FW_WR1 + j * 68 + 64], v);
                v = fmaf(cy, ws[FW_WR1 + j * 68 + 65], v);
                v = fmaf(cz, ws[FW_WR1 + j * 68 + 66], v);
                v = fmaf(cw, ws[FW_WR1 + j * 68 + 67], v);
                v = fmaxf(v, 0.f);
                partial = fmaf(v, ws[FW_WR2 + j], partial);
            }
            float tot = partial + __shfl_xor_sync(0xffffffffu, partial, 1);
            int li = loc - lbase;
            if (li >= 0 && li < lcnt) alsh[li] = tot;
        }
        int att = sample_lp_pair<13>(alsh, lbase, lcnt, 25, keys.a[6], keys.b[6], b, alp1);

        if (p == 0) {
            int4 ro = *(const int4*)(canvas0 + (b * 25 + att) * 4);
            int4 rf = *(const int4*)(refp + b * 4);
            float att_rew = (ro.x == rf.x && ro.y == rf.y && ro.z == rf.z && ro.w == rf.w)
                                ? 1.f : -1.f;
            int loc1 = (ro.z + c_offx[ls1]) * 5 + (ro.w + c_offy[ls1]);
            int l1c = min(max(loc1, 0), 24);
            int4 pt1 = *(const int4*)(canvas1 + (b * 25 + l1c) * 4);
            bool ok1 = (loc1 >= 0) && (loc1 < 25) && ((pt1.x + pt1.y + pt1.z + pt1.w) >= 0);
            float loc_r1 = ok1 ? 1.f : -1.f;
            float col_r1 = ok1 ? ((cs1 == pt1.x) ? 1.f : -1.f) : 0.f;

            out[3 * BN + b] = clp1;
            out[4 * BN + b] = slp1;
            out[5 * BN + b] = llp1;
            out[6 * BN + b] = alp1;
            out[(7 + 3) * BN + b] = loc_r1;
            out[(7 + 4) * BN + b] = col_r1;
            out[(7 + 5) * BN + b] = loc_r1;
            out[(7 + 6) * BN + b] = att_rew;
        }
    }
}

// ================= launch =================
extern "C" void kernel_launch(void* const* d_in, const int* in_sizes, int n_in,
                              void* d_out, int out_size) {
    const int*   inst0   = (const int*)d_in[0];
    const int*   inst1   = (const int*)d_in[1];
    const int*   canvas0 = (const int*)d_in[2];
    const int*   canvas1 = (const int*)d_in[3];
    const int*   refp    = (const int*)d_in[4];
    const float* embed   = (const float*)d_in[5];
    const float* W_ih    = (const float*)d_in[6];
    const float* W_hh    = (const float*)d_in[7];
    const float* b_ih    = (const float*)d_in[8];
    const float* b_hh    = (const float*)d_in[9];
    const float* Wc      = (const float*)d_in[10];
    const float* bc      = (const float*)d_in[11];
    const float* Ws      = (const float*)d_in[12];
    const float* bs      = (const float*)d_in[13];
    const float* Wl      = (const float*)d_in[14];
    const float* bl      = (const float*)d_in[15];
    const float* Wr1     = (const float*)d_in[16];
    const float* br1     = (const float*)d_in[17];
    const float* Wr2     = (const float*)d_in[18];
    const float* br2     = (const float*)d_in[19];
    const float* Wp      = (const float*)d_in[20];
    const float* bp      = (const float*)d_in[21];

    Keys keys;
#if THREEFRY_PARTITIONABLE
    for (int i = 0; i < 7; i++)
        threefry2x32(0u, 42u, 0u, (uint32_t)i, keys.a[i], keys.b[i]);
#else
    uint32_t o[14];
    for (int i = 0; i < 7; i++)
        threefry2x32(0u, 42u, (uint32_t)i, (uint32_t)(i + 7), o[i], o[7 + i]);
    for (int i = 0; i < 7; i++) { keys.a[i] = o[2 * i]; keys.b[i] = o[2 * i + 1]; }
#endif

    cudaFuncSetAttribute(lstm_kernel, cudaFuncAttributeMaxDynamicSharedMemorySize,
                         LSTM_SMEM_BYTES);

    tokgate_kernel<<<(VOCAB + 7) / 8, 256>>>(embed, W_ih, b_ih, b_hh);
    wlof_kernel<<<16, 256>>>(W_hh);
    lstm_kernel<<<dim3(BN / TBM, 2), 256, LSTM_SMEM_BYTES>>>(
        inst0, inst1, W_hh, canvas0, canvas1, refp,
        Wc, bc, Ws, bs, Wl, bl, Wr1, br1, Wr2, br2, Wp, bp,
        (float*)d_out, keys);
}

// round 17
// speedup vs baseline: 1.1653x; 1.1653x over previous
#include <cuda_runtime.h>
#include <cuda_fp16.h>
#include <cstdint>

#define BN 16384
#define SEQ 32
#define RNN 64
#define NG 256
#define VOCAB 1001
#define TBM 32             // samples per LSTM CTA
#define HT 128             // heads: 2 threads per sample, 64 samples per block
#define EXACT_FROM 31      // steps >= this use full 3-product compensation
#define THREEFRY_PARTITIONABLE 1

typedef unsigned long long u64;

__device__ float g_h[2 * BN * RNN];
__device__ float g_tokgate[VOCAB * NG];
// Wlo B-fragments, pre-swizzled for coalesced warp loads:
// index ((nb*4+kt)*8+nt)*32 + lane
__device__ uint2 g_WloF[4 * 4 * 8 * 32];

// ================= threefry2x32 (exact JAX algorithm) =================
__host__ __device__ __forceinline__ uint32_t rotl32(uint32_t x, int d) {
    return (x << d) | (x >> (32 - d));
}
__host__ __device__ __forceinline__ void threefry2x32(uint32_t k0, uint32_t k1,
                                                      uint32_t c0, uint32_t c1,
                                                      uint32_t& o0, uint32_t& o1) {
    uint32_t ks2 = k0 ^ k1 ^ 0x1BD11BDAu;
    uint32_t x0 = c0 + k0, x1 = c1 + k1;
#define TF_R4(a,b,c,d) \
    x0 += x1; x1 = rotl32(x1,a); x1 ^= x0; \
    x0 += x1; x1 = rotl32(x1,b); x1 ^= x0; \
    x0 += x1; x1 = rotl32(x1,c); x1 ^= x0; \
    x0 += x1; x1 = rotl32(x1,d); x1 ^= x0;
    TF_R4(13,15,26,6);  x0 += k1;  x1 += ks2 + 1u;
    TF_R4(17,29,16,24); x0 += ks2; x1 += k0  + 2u;
    TF_R4(13,15,26,6);  x0 += k0;  x1 += k1  + 3u;
    TF_R4(17,29,16,24); x0 += k1;  x1 += ks2 + 4u;
    TF_R4(13,15,26,6);  x0 += ks2; x1 += k0  + 5u;
#undef TF_R4
    o0 = x0; o1 = x1;
}

struct Keys { uint32_t a[7]; uint32_t b[7]; };

__device__ __forceinline__ uint32_t jax_bits32(uint32_t k0, uint32_t k1,
                                               uint32_t idx, uint32_t half) {
#if THREEFRY_PARTITIONABLE
    uint32_t y0, y1;
    threefry2x32(k0, k1, 0u, idx, y0, y1);
    return y0 ^ y1;
#else
    uint32_t p = (idx < half) ? idx : idx - half;
    uint32_t y0, y1;
    threefry2x32(k0, k1, p, p + half, y0, y1);
    return (idx < half) ? y0 : y1;
#endif
}
__device__ __forceinline__ float jax_gumbel(uint32_t k0, uint32_t k1,
                                            uint32_t idx, uint32_t half) {
    uint32_t bits = jax_bits32(k0, k1, idx, half);
    float f = __uint_as_float((bits >> 9) | 0x3f800000u) - 1.0f;
    f = fmaxf(f, 1.17549435e-38f);
    return -logf(-logf(f));
}

// ---- MUFU-based fast activations (LSTM cell only) ----
__device__ __forceinline__ float fsig(float x) {
    return __fdividef(1.0f, 1.0f + __expf(-x));
}
__device__ __forceinline__ float ftanh(float x) {
    float xc = fminf(fmaxf(x, -12.0f), 12.0f);
    float t = __expf(2.0f * xc);
    return __fdividef(t - 1.0f, t + 1.0f);
}

// mma.sync m16n8k16 f16 (baseline PTX)
__device__ __forceinline__ void mma_f16(float d[4], const uint32_t a[4],
                                        uint32_t b0, uint32_t b1) {
    asm volatile(
        "mma.sync.aligned.m16n8k16.row.col.f32.f16.f16.f32 "
        "{%0,%1,%2,%3}, {%4,%5,%6,%7}, {%8,%9}, {%0,%1,%2,%3};"
        : "+f"(d[0]), "+f"(d[1]), "+f"(d[2]), "+f"(d[3])
        : "r"(a[0]), "r"(a[1]), "r"(a[2]), "r"(a[3]), "r"(b0), "r"(b1));
}

__device__ __forceinline__ uint32_t pack_h2(__half lo_h, __half hi_h) {
    __half2 h2 = __halves2half2(lo_h, hi_h);
    return *(uint32_t*)&h2;
}

// ================= prep kernel: tokgate (blocks 0..125) + WloF (blocks 126..141) ====
#define TG_BLOCKS ((VOCAB + 7) / 8)   // 126
__global__ void __launch_bounds__(256)
prep_kernel(const float* __restrict__ embed, const float* __restrict__ W_ih,
            const float* __restrict__ b_ih, const float* __restrict__ b_hh,
            const float* __restrict__ W_hh) {
    __shared__ float e[8][64];
    const int tid = threadIdx.x;
    if (blockIdx.x < TG_BLOCKS) {
        // ---- tokgate: g_tokgate[v][c], c = 4u+g ----
        const int v0 = blockIdx.x * 8;
        for (int i = tid; i < 8 * 64; i += 256) {
            int vv = v0 + (i >> 6);
            e[i >> 6][i & 63] = (vv < VOCAB) ? embed[vv * 64 + (i & 63)] : 0.f;
        }
        __syncthreads();
        const int c = tid, gg = c & 3, u = c >> 2;
        const int row = gg * 64 + u;
        float wreg[64];
        const float4* wp = (const float4*)(W_ih + row * 64);
#pragma unroll
        for (int i = 0; i < 16; i++) {
            float4 w4 = wp[i];
            wreg[4 * i] = w4.x; wreg[4 * i + 1] = w4.y;
            wreg[4 * i + 2] = w4.z; wreg[4 * i + 3] = w4.w;
        }
        const float bias = b_ih[row] + b_hh[row];
#pragma unroll
        for (int j = 0; j < 8; j++) {
            int v = v0 + j;
            if (v >= VOCAB) break;
            float d = bias;
#pragma unroll
            for (int k = 0; k < 64; k++) d = fmaf(e[j][k], wreg[k], d);
            g_tokgate[v * NG + c] = d;
        }
    } else {
        // ---- WloF fragment table ----
        int idx = (blockIdx.x - TG_BLOCKS) * 256 + tid;   // 0..4095
        int lane = idx & 31, nt = (idx >> 5) & 7, kt = (idx >> 8) & 3, nb = (idx >> 10) & 3;
        int gid = lane >> 2, tig = lane & 3;
        int c = nb * 64 + nt * 8 + gid;
        int cnb = c >> 6, cnt = (c >> 3) & 7, cup = (c >> 2) & 1, cg = c & 3;
        int u = cnb * 16 + cnt * 2 + cup;
        const float* wr = W_hh + (cg * 64 + u) * 64;
        uint2 v;
        {
            int kp = kt * 8 + tig;
            float w0 = wr[2 * kp], w1 = wr[2 * kp + 1];
            __half h0 = __float2half_rn(w0), h1 = __float2half_rn(w1);
            v.x = pack_h2(__float2half_rn(w0 - __half2float(h0)),
                          __float2half_rn(w1 - __half2float(h1)));
        }
        {
            int kp = kt * 8 + tig + 4;
            float w0 = wr[2 * kp], w1 = wr[2 * kp + 1];
            __half h0 = __float2half_rn(w0), h1 = __float2half_rn(w1);
            v.y = pack_h2(__float2half_rn(w0 - __half2float(h0)),
                          __float2half_rn(w1 - __half2float(h1)));
        }
        g_WloF[idx] = v;
    }
}

// ================= LSTM kernel (R12/R14 structure: 3 CTAs/SM) =================
#define WSTR 36
#define OFF_WHI 0
#define OFF_H   (256 * WSTR)
#define OFF_TOK (OFF_H + 4 * TBM * WSTR)
#define LSTM_SMEM_WORDS (OFF_TOK + TBM * SEQ)
#define LSTM_SMEM_BYTES (LSTM_SMEM_WORDS * 4)
// column order: c' = nb*64 + nt*8 + 4*up + g ; unit u = nb*16 + nt*2 + up

__global__ void __launch_bounds__(256, 3)
lstm_kernel(const int* __restrict__ inst0, const int* __restrict__ inst1,
            const float* __restrict__ W_hh) {
    extern __shared__ uint32_t smw[];
    uint32_t* Whi = smw + OFF_WHI;
    int*      tok = (int*)(smw + OFF_TOK);    // [s][t]

    const int tid  = threadIdx.x;
    const int wid  = tid >> 5, lane = tid & 31;
    const int gid  = lane >> 2, tig = lane & 3;
    const int mb   = wid & 1;
    const int nb   = wid >> 1;
    const int base = blockIdx.x * TBM;
    const int* inst = (blockIdx.y == 0) ? inst0 : inst1;
    float* hout = g_h + blockIdx.y * (BN * RNN);

    for (int idx = tid; idx < NG * 32; idx += 256) {
        int c = idx >> 5, kp = idx & 31;
        int cnb = c >> 6, cnt = (c >> 3) & 7, cup = (c >> 2) & 1, cg = c & 3;
        int u = cnb * 16 + cnt * 2 + cup;
        const float* wr = W_hh + (cg * 64 + u) * 64 + 2 * kp;
        Whi[c * WSTR + kp] = pack_h2(__float2half_rn(wr[0]), __float2half_rn(wr[1]));
    }
    for (int idx = tid; idx < TBM * SEQ; idx += 256)
        tok[idx] = inst[base * SEQ + idx];
    __syncthreads();

    const int row   = mb * 16 + gid + 8 * (tig & 1);
    const int upair = tig >> 1;
    const int m0    = mb * 16;
    const int cn0   = nb * 64;
    float c_reg[8];
#pragma unroll
    for (int i = 0; i < 8; i++) c_reg[i] = 0.f;

    for (int t = 0; t < SEQ; t++) {
        uint32_t* Hr_hi = smw + OFF_H + (t & 1) * (2 * TBM * WSTR);
        uint32_t* Hr_lo = Hr_hi + TBM * WSTR;
        uint32_t* Hw_hi = smw + OFF_H + ((t + 1) & 1) * (2 * TBM * WSTR);
        uint32_t* Hw_lo = Hw_hi + TBM * WSTR;
        __half* HWh = (__half*)Hw_hi;
        __half* HWl = (__half*)Hw_lo;

        const int tv = tok[row * SEQ + t];
        const float4* tgp = (const float4*)(g_tokgate + tv * NG);

        float d[8][4];
#pragma unroll
        for (int nt = 0; nt < 8; nt++)
#pragma unroll
            for (int j = 0; j < 4; j++) d[nt][j] = 0.f;

        if (t > 0) {
            const bool exact = (t >= EXACT_FROM);
#pragma unroll
            for (int kt = 0; kt < 4; kt++) {
                const int kp0 = kt * 8 + tig;
                uint32_t ahi[4];
                ahi[0] = Hr_hi[(m0 + gid)     * WSTR + kp0];
                ahi[1] = Hr_hi[(m0 + gid + 8) * WSTR + kp0];
                ahi[2] = Hr_hi[(m0 + gid)     * WSTR + kp0 + 4];
                ahi[3] = Hr_hi[(m0 + gid + 8) * WSTR + kp0 + 4];

                uint32_t bh[8][2];
#pragma unroll
                for (int nt = 0; nt < 8; nt++) {
                    const int c = cn0 + nt * 8 + gid;
                    bh[nt][0] = Whi[c * WSTR + kp0];
                    bh[nt][1] = Whi[c * WSTR + kp0 + 4];
                    mma_f16(d[nt], ahi, bh[nt][0], bh[nt][1]);   // hi . Whi
                }
                if (exact) {
                    uint32_t alo[4];
                    alo[0] = Hr_lo[(m0 + gid)     * WSTR + kp0];
                    alo[1] = Hr_lo[(m0 + gid + 8) * WSTR + kp0];
                    alo[2] = Hr_lo[(m0 + gid)     * WSTR + kp0 + 4];
                    alo[3] = Hr_lo[(m0 + gid + 8) * WSTR + kp0 + 4];
#pragma unroll
                    for (int nt = 0; nt < 8; nt++)
                        mma_f16(d[nt], alo, bh[nt][0], bh[nt][1]);  // lo . Whi
                    const uint2* wlo = g_WloF + ((nb * 4 + kt) * 8) * 32 + lane;
#pragma unroll
                    for (int nt = 0; nt < 8; nt++) {
                        uint2 bl = wlo[nt * 32];                    // coalesced LDG.64
                        mma_f16(d[nt], ahi, bl.x, bl.y);            // hi . Wlo
                    }
                }
            }
        }

        // ---- epilogue: 2-shfl quad-exchange, + tokgate, LSTM cell (MUFU), store ----
        const bool e = (tig & 1) == 0;
        const bool store_lo = (t >= EXACT_FROM - 1);

#pragma unroll
        for (int nt = 0; nt < 8; nt++) {
            float x0 = e ? d[nt][2] : d[nt][0];
            float x1 = e ? d[nt][3] : d[nt][1];
            float s0 = __shfl_xor_sync(0xffffffffu, x0, 1);
            float s1 = __shfl_xor_sync(0xffffffffu, x1, 1);
            float ig = e ? d[nt][0] : s0;
            float fg = e ? d[nt][1] : s1;
            float gg = e ? s0 : d[nt][2];
            float og = e ? s1 : d[nt][3];
            const int u = nb * 16 + nt * 2 + upair;
            float4 tgv = tgp[u];
            ig += tgv.x; fg += tgv.y; gg += tgv.z; og += tgv.w;
            float cb = fsig(fg) * c_reg[nt] + fsig(ig) * ftanh(gg);
            float h = fsig(og) * ftanh(cb);
            c_reg[nt] = cb;
            __half hh = __float2half_rn(h);
            HWh[row * (2 * WSTR) + u] = hh;
            if (store_lo)
                HWl[row * (2 * WSTR) + u] = __float2half_rn(h - __half2float(hh));
            if (t == SEQ - 1) hout[(base + row) * RNN + u] = h;
        }
        __syncthreads();
    }
}

// ================= heads kernel: 2 threads per sample, reg-capped =========
#define HW_WC   0
#define HW_BC   (HW_WC + 192)
#define HW_WS   (HW_BC + 4)
#define HW_BS   (HW_WS + 192)
#define HW_WL   (HW_BS + 4)
#define HW_BL   (HW_WL + 1600)
#define HW_WP   (HW_BL + 28)
#define HW_BP   (HW_WP + 512)
#define HW_WR1  (HW_BP + 8)
#define HW_BR1  (HW_WR1 + 2176)
#define HW_WR2  (HW_BR1 + 32)
#define HW_BR2  (HW_WR2 + 32)
#define HW_HB   (HW_BR2 + 4)
#define SPB 64   // samples per block
#define HEADS_SMEM_FLOATS (HW_HB + SPB * 65)
#define HEADS_SMEM_BYTES  (HEADS_SMEM_FLOATS * 4)

__device__ const int c_offx[8] = {-1, 1, 0, 0, -1, -1, 1, 1};
__device__ const int c_offy[8] = {0, 0, 1, -1, -1, 1, -1, 1};

// Pair-split categorical sample (proven R12/R14)
template <int MAXC>
__device__ __forceinline__ int sample_lp_pair(const float* lg, int vbase, int vcnt,
                                              int V, uint32_t k0, uint32_t k1,
                                              int b, float& lp) {
    const uint32_t half = (uint32_t)(BN * V / 2);
    float bestz = -1e30f, bestl = -1e30f, m = -1e30f;
    int bestv = 0;
#pragma unroll
    for (int i = 0; i < MAXC; i++) {
        if (i >= vcnt) break;
        int v = vbase + i;
        float z = lg[i] + jax_gumbel(k0, k1, (uint32_t)(b * V + v), half);
        if (z > bestz) { bestz = z; bestv = v; bestl = lg[i]; }
        m = fmaxf(m, lg[i]);
    }
    m = fmaxf(m, __shfl_xor_sync(0xffffffffu, m, 1));
    float ssum = 0.f;
#pragma unroll
    for (int i = 0; i < MAXC; i++) {
        if (i >= vcnt) break;
        ssum += expf(lg[i] - m);
    }
    ssum += __shfl_xor_sync(0xffffffffu, ssum, 1);
    float zo = __shfl_xor_sync(0xffffffffu, bestz, 1);
    int   vo = __shfl_xor_sync(0xffffffffu, bestv, 1);
    float lo = __shfl_xor_sync(0xffffffffu, bestl, 1);
    if (zo > bestz) { bestv = vo; bestl = lo; }
    lp = (bestl - m) - logf(ssum);
    return bestv;
}

__global__ void __launch_bounds__(HT, 4)   // cap regs at 128
heads_kernel(const int* __restrict__ canvas0, const int* __restrict__ canvas1,
             const int* __restrict__ refp,
             const float* __restrict__ Wc, const float* __restrict__ bc,
             const float* __restrict__ Ws, const float* __restrict__ bs,
             const float* __restrict__ Wl, const float* __restrict__ bl,
             const float* __restrict__ Wr1, const float* __restrict__ br1,
             const float* __restrict__ Wr2, const float* __restrict__ br2,
             const float* __restrict__ Wp, const float* __restrict__ bp,
             float* __restrict__ out, Keys keys) {
    extern __shared__ float sm[];
    const int tid  = threadIdx.x;
    const int p    = tid & 1;            // half-index within sample pair
    const int sidx = tid >> 1;           // sample within block
    const int b    = blockIdx.x * SPB + sidx;
    const int tile = blockIdx.x * SPB;
    const int dialog = blockIdx.y;

    for (int i = tid; i < 192;  i += HT) sm[HW_WC + i] = Wc[i];
    for (int i = tid; i < 192;  i += HT) sm[HW_WS + i] = Ws[i];
    if (tid < 3)  sm[HW_BC + tid]  = bc[tid];
    if (tid < 3)  sm[HW_BS + tid]  = bs[tid];
    if (dialog == 0) {
        for (int i = tid; i < 1600; i += HT) sm[HW_WL + i] = Wl[i];
        if (tid < 25) sm[HW_BL + tid]  = bl[tid];
    } else {
        for (int i = tid; i < 512;  i += HT) sm[HW_WP + i] = Wp[i];
        for (int i = tid; i < 2176; i += HT) sm[HW_WR1 + i] = Wr1[i];
        if (tid < 8)  sm[HW_BP + tid]  = bp[tid];
        if (tid < 32) sm[HW_BR1 + tid] = br1[tid];
        if (tid < 32) sm[HW_WR2 + tid] = Wr2[tid];
        if (tid == 0) sm[HW_BR2] = br2[0];
    }

    float* hb = sm + HW_HB;
    for (int i = tid; i < SPB * RNN; i += HT) {
        int s = i >> 6, k = i & 63;
        hb[s * 65 + k] = g_h[dialog * (BN * RNN) + (tile + s) * RNN + k];
    }
    __syncthreads();

    const float* h = hb + sidx * 65;

    // color/shape logits, split 2/1 across the pair
    const int cbase = p ? 2 : 0;
    const int ccnt  = p ? 1 : 2;
    float lgc[2], lgs[2];
#pragma unroll
    for (int i = 0; i < 2; i++) {
        if (i >= ccnt) break;
        int r = cbase + i;
        float dd = 0.f, ee = 0.f;
        for (int k = 0; k < 64; k++) {
            dd = fmaf(h[k], sm[HW_WC + r * 64 + k], dd);
            ee = fmaf(h[k], sm[HW_WS + r * 64 + k], ee);
        }
        lgc[i] = dd + sm[HW_BC + r];
        lgs[i] = ee + sm[HW_BS + r];
    }

    const int lbase = p ? 13 : 0;
    const int lcnt  = p ? 12 : 13;

    if (dialog == 0) {
        // 25-way location logits, split 13/12
        float ll[13];
#pragma unroll
        for (int i = 0; i < 13; i++) {
            if (i >= lcnt) break;
            int r = lbase + i;
            float dd = 0.f;
            for (int k = 0; k < 64; k++) dd = fmaf(h[k], sm[HW_WL + r * 64 + k], dd);
            ll[i] = dd + sm[HW_BL + r];
        }
        float clp0, slp0, llp0;
        int cs0  = sample_lp_pair<2>(lgc, cbase, ccnt, 3, keys.a[0], keys.b[0], b, clp0);
        sample_lp_pair<2>(lgs, cbase, ccnt, 3, keys.a[1], keys.b[1], b, slp0);
        int loc0 = sample_lp_pair<13>(ll, lbase, lcnt, 25, keys.a[2], keys.b[2], b, llp0);

        if (p == 0) {
            int lclip = min(max(loc0, 0), 24);
            int4 pt = *(const int4*)(canvas1 + (b * 25 + lclip) * 4);
            bool ok0 = (loc0 >= 0) && (loc0 < 25) && ((pt.x + pt.y + pt.z + pt.w) >= 0);
            float loc_r0 = ok0 ? 1.f : -1.f;
            float col_r0 = ok0 ? ((cs0 == pt.x) ? 1.f : -1.f) : 0.f;

            out[0 * BN + b] = clp0;
            out[1 * BN + b] = slp0;
            out[2 * BN + b] = llp0;
            out[(7 + 0) * BN + b] = loc_r0;
            out[(7 + 1) * BN + b] = col_r0;
            out[(7 + 2) * BN + b] = loc_r0;
        }
    } else {
        // 8-way offset logits, split 4/4
        float lp8[4];
        const int pbase = p * 4;
#pragma unroll
        for (int i = 0; i < 4; i++) {
            int r = pbase + i;
            float dd = 0.f;
            for (int k = 0; k < 64; k++) dd = fmaf(h[k], sm[HW_WP + r * 64 + k], dd);
            lp8[i] = dd + sm[HW_BP + r];
        }
        float clp1, slp1, llp1, alp1;
        int cs1 = sample_lp_pair<2>(lgc, cbase, ccnt, 3, keys.a[3], keys.b[3], b, clp1);
        sample_lp_pair<2>(lgs, cbase, ccnt, 3, keys.a[4], keys.b[4], b, slp1);
        int ls1 = sample_lp_pair<4>(lp8, pbase, 4, 8, keys.a[5], keys.b[5], b, llp1);

        // attention MLP: this thread owns hidden units j0..j0+15
        const int j0 = p * 16;
        float pre[16];
#pragma unroll
        for (int jj = 0; jj < 16; jj++) {
            int j = j0 + jj;
            float dd = 0.f;
            for (int k = 0; k < 64; k++) dd = fmaf(h[k], sm[HW_WR1 + j * 68 + k], dd);
            pre[jj] = dd + sm[HW_BR1 + j];
        }
        float alsh[13];
#pragma unroll 5
        for (int loc = 0; loc < 25; loc++) {
            int4 cv = *(const int4*)(canvas0 + (b * 25 + loc) * 4);
            float cx = (float)cv.x, cy = (float)cv.y, cz = (float)cv.z, cw = (float)cv.w;
            float partial = p ? 0.f : sm[HW_BR2];
#pragma unroll
            for (int jj = 0; jj < 16; jj++) {
                int j = j0 + jj;
                float v = pre[jj];
                v = fmaf(cx, sm[HW_WR1 + j * 68 + 64], v);
                v = fmaf(cy, sm[HW_WR1 + j * 68 + 65], v);
                v = fmaf(cz, sm[HW_WR1 + j * 68 + 66], v);
                v = fmaf(cw, sm[HW_WR1 + j * 68 + 67], v);
                v = fmaxf(v, 0.f);
                partial = fmaf(v, sm[HW_WR2 + j], partial);
            }
            float tot = partial + __shfl_xor_sync(0xffffffffu, partial, 1);
            int li = loc - lbase;
            if (li >= 0 && li < lcnt) alsh[li] = tot;
        }
        int att = sample_lp_pair<13>(alsh, lbase, lcnt, 25, keys.a[6], keys.b[6], b, alp1);

        if (p == 0) {
            int4 ro = *(const int4*)(canvas0 + (b * 25 + att) * 4);
            int4 rf = *(const int4*)(refp + b * 4);
            float att_rew = (ro.x == rf.x && ro.y == rf.y && ro.z == rf.z && ro.w == rf.w)
                                ? 1.f : -1.f;
            int loc1 = (ro.z + c_offx[ls1]) * 5 + (ro.w + c_offy[ls1]);
            int l1c = min(max(loc1, 0), 24);
            int4 pt1 = *(const int4*)(canvas1 + (b * 25 + l1c) * 4);
            bool ok1 = (loc1 >= 0) && (loc1 < 25) && ((pt1.x + pt1.y + pt1.z + pt1.w) >= 0);
            float loc_r1 = ok1 ? 1.f : -1.f;
            float col_r1 = ok1 ? ((cs1 == pt1.x) ? 1.f : -1.f) : 0.f;

            out[3 * BN + b] = clp1;
            out[4 * BN + b] = slp1;
            out[5 * BN + b] = llp1;
            out[6 * BN + b] = alp1;
            out[(7 + 3) * BN + b] = loc_r1;
            out[(7 + 4) * BN + b] = col_r1;
            out[(7 + 5) * BN + b] = loc_r1;
            out[(7 + 6) * BN + b] = att_rew;
        }
    }
}

// ================= launch =================
extern "C" void kernel_launch(void* const* d_in, const int* in_sizes, int n_in,
                              void* d_out, int out_size) {
    const int*   inst0   = (const int*)d_in[0];
    const int*   inst1   = (const int*)d_in[1];
    const int*   canvas0 = (const int*)d_in[2];
    const int*   canvas1 = (const int*)d_in[3];
    const int*   refp    = (const int*)d_in[4];
    const float* embed   = (const float*)d_in[5];
    const float* W_ih    = (const float*)d_in[6];
    const float* W_hh    = (const float*)d_in[7];
    const float* b_ih    = (const float*)d_in[8];
    const float* b_hh    = (const float*)d_in[9];
    const float* Wc      = (const float*)d_in[10];
    const float* bc      = (const float*)d_in[11];
    const float* Ws      = (const float*)d_in[12];
    const float* bs      = (const float*)d_in[13];
    const float* Wl      = (const float*)d_in[14];
    const float* bl      = (const float*)d_in[15];
    const float* Wr1     = (const float*)d_in[16];
    const float* br1     = (const float*)d_in[17];
    const float* Wr2     = (const float*)d_in[18];
    const float* br2     = (const float*)d_in[19];
    const float* Wp      = (const float*)d_in[20];
    const float* bp      = (const float*)d_in[21];

    Keys keys;
#if THREEFRY_PARTITIONABLE
    for (int i = 0; i < 7; i++)
        threefry2x32(0u, 42u, 0u, (uint32_t)i, keys.a[i], keys.b[i]);
#else
    uint32_t o[14];
    for (int i = 0; i < 7; i++)
        threefry2x32(0u, 42u, (uint32_t)i, (uint32_t)(i + 7), o[i], o[7 + i]);
    for (int i = 0; i < 7; i++) { keys.a[i] = o[2 * i]; keys.b[i] = o[2 * i + 1]; }
#endif

    cudaFuncSetAttribute(lstm_kernel, cudaFuncAttributeMaxDynamicSharedMemorySize,
                         LSTM_SMEM_BYTES);
    cudaFuncSetAttribute(heads_kernel, cudaFuncAttributeMaxDynamicSharedMemorySize,
                         HEADS_SMEM_BYTES);

    prep_kernel<<<TG_BLOCKS + 16, 256>>>(embed, W_ih, b_ih, b_hh, W_hh);
    lstm_kernel<<<dim3(BN / TBM, 2), 256, LSTM_SMEM_BYTES>>>(inst0, inst1, W_hh);
    heads_kernel<<<dim3(BN / SPB, 2), HT, HEADS_SMEM_BYTES>>>(
        canvas0, canvas1, refp, Wc, bc, Ws, bs, Wl, bl, Wr1, br1, Wr2, br2,
        Wp, bp, (float*)d_out, keys);
}